// round 15
// baseline (speedup 1.0000x reference)
#include <cuda_runtime.h>
#include <cstdint>

#define N_V   8192
#define C_CH  4
#define F_IN  512
#define F_OUT 64
#define K_TOP 16
#define ROWS  (N_V * C_CH)      // 32768
#define ROWLEN N_V              // 8192 attention cols per row
#define ROWBYTES (ROWLEN * 4)   // 32 KB
#define TPB   256
#define CAP   512               // candidate buffer (expected ~51, sigma ~7)
#define CAP2  256               // post-threshold candidates
#define G_TOPK (148 * 3)        // persistent grid: 3 blocks/SM

#define SPEC_F     2.5f         // speculative floor; p=0.0062 per element
#define BASE16_SP  0xC020u      // keyhi16 of 2.5f: (0x4020 | 0x8000)

// scratch for h = x @ W   (2 MB static device array; no allocation)
__device__ float g_h[N_V * F_OUT];

// monotone key transform: order-preserving float -> uint
__device__ __forceinline__ uint32_t f2key(uint32_t b) {
    return b ^ ((uint32_t)((int32_t)b >> 31) | 0x80000000u);
}
__device__ __forceinline__ float key2f(uint32_t k) {
    uint32_t b = (k & 0x80000000u) ? (k ^ 0x80000000u) : ~k;
    return __uint_as_float(b);
}
__device__ __forceinline__ uint32_t smem_u32(const void* p) {
    uint32_t a;
    asm("{ .reg .u64 t; cvta.to.shared.u64 t, %1; cvt.u32.u64 %0, t; }"
        : "=r"(a) : "l"(p));
    return a;
}

// ---------------------------------------------------------------------------
// GEMM: h[8192,64] = x[8192,512] @ W[512,64]  (R13 shape, ~25us)
// ---------------------------------------------------------------------------
#define BM 64
#define BK 32
__global__ __launch_bounds__(TPB) void gemm_kernel(const float* __restrict__ x,
                                                   const float* __restrict__ W) {
    __shared__ float xs[BM][BK + 4];
    __shared__ float ws[BK][F_OUT];
    int tid = threadIdx.x;
    int tx = tid & 15;
    int ty = tid >> 4;
    int r0 = blockIdx.x * BM;
    float acc[4][4];
    #pragma unroll
    for (int i = 0; i < 4; i++)
        #pragma unroll
        for (int j = 0; j < 4; j++) acc[i][j] = 0.f;

    for (int k0 = 0; k0 < F_IN; k0 += BK) {
        #pragma unroll
        for (int i = 0; i < 2; i++) {
            int idx = tid + TPB * i;
            int row = idx >> 3;
            int k4  = idx & 7;
            float4 v = *(const float4*)(x + (size_t)(r0 + row) * F_IN + k0 + k4 * 4);
            *(float4*)&xs[row][k4 * 4] = v;
        }
        #pragma unroll
        for (int i = 0; i < 2; i++) {
            int idx = tid + TPB * i;
            int kk = idx >> 4;
            int f4 = idx & 15;
            *(((float4*)&ws[kk][0]) + f4) =
                *(const float4*)(W + (size_t)(k0 + kk) * F_OUT + f4 * 4);
        }
        __syncthreads();
        #pragma unroll
        for (int kk0 = 0; kk0 < BK; kk0 += 4) {
            float4 a0 = *(const float4*)&xs[ty * 4 + 0][kk0];
            float4 a1 = *(const float4*)&xs[ty * 4 + 1][kk0];
            float4 a2 = *(const float4*)&xs[ty * 4 + 2][kk0];
            float4 a3 = *(const float4*)&xs[ty * 4 + 3][kk0];
            float4 b0 = *(((const float4*)&ws[kk0 + 0][0]) + tx);
            float4 b1 = *(((const float4*)&ws[kk0 + 1][0]) + tx);
            float4 b2 = *(((const float4*)&ws[kk0 + 2][0]) + tx);
            float4 b3 = *(((const float4*)&ws[kk0 + 3][0]) + tx);
            #define FMA4(ai, bq) \
                acc[0][0]=fmaf(a0.ai,bq.x,acc[0][0]); acc[0][1]=fmaf(a0.ai,bq.y,acc[0][1]); \
                acc[0][2]=fmaf(a0.ai,bq.z,acc[0][2]); acc[0][3]=fmaf(a0.ai,bq.w,acc[0][3]); \
                acc[1][0]=fmaf(a1.ai,bq.x,acc[1][0]); acc[1][1]=fmaf(a1.ai,bq.y,acc[1][1]); \
                acc[1][2]=fmaf(a1.ai,bq.z,acc[1][2]); acc[1][3]=fmaf(a1.ai,bq.w,acc[1][3]); \
                acc[2][0]=fmaf(a2.ai,bq.x,acc[2][0]); acc[2][1]=fmaf(a2.ai,bq.y,acc[2][1]); \
                acc[2][2]=fmaf(a2.ai,bq.z,acc[2][2]); acc[2][3]=fmaf(a2.ai,bq.w,acc[2][3]); \
                acc[3][0]=fmaf(a3.ai,bq.x,acc[3][0]); acc[3][1]=fmaf(a3.ai,bq.y,acc[3][1]); \
                acc[3][2]=fmaf(a3.ai,bq.z,acc[3][2]); acc[3][3]=fmaf(a3.ai,bq.w,acc[3][3]);
            FMA4(x, b0)
            FMA4(y, b1)
            FMA4(z, b2)
            FMA4(w, b3)
            #undef FMA4
        }
        __syncthreads();
    }
    #pragma unroll
    for (int i = 0; i < 4; i++) {
        float4 o = make_float4(acc[i][0], acc[i][1], acc[i][2], acc[i][3]);
        *(float4*)(g_h + (size_t)(r0 + ty * 4 + i) * F_OUT + tx * 4) = o;
    }
}

// ---------------------------------------------------------------------------
// Persistent double-buffered TMA top-16 kernel.
// 444 blocks, each loops over rows stride G_TOPK; row i+1 streams into the
// other buffer while row i is processed; buffer re-armed right after use.
// ---------------------------------------------------------------------------
__global__ __launch_bounds__(TPB) void topk_kernel(const float* __restrict__ att,
                                                   float* __restrict__ out) {
    extern __shared__ __align__(128) char dynbuf[];   // 2 x 32 KB row buffers
    __shared__ __align__(8) unsigned long long s_mbar[2];
    __shared__ uint32_t cand[CAP];     // packed: keyhi16<<16 | col
    __shared__ uint32_t hist32[32];
    __shared__ uint32_t hist[256];     // fallback coarse hist
    __shared__ uint32_t sfx[257];      // fallback suffix scan
    __shared__ uint32_t wsfx[8];
    __shared__ int      s_cnt;
    __shared__ int      s_nf;
    __shared__ uint32_t s_thr16;
    __shared__ int      s_cb8;
    __shared__ uint16_t fc[CAP2];
    __shared__ uint32_t fkk[CAP2];
    __shared__ uint32_t selk[16];
    __shared__ int      seli[16];
    __shared__ float    s_w[16];
    __shared__ float    partial[4][64];

    int tid  = threadIdx.x;
    int lane = tid & 31;
    int wid  = tid >> 5;
    int bid  = blockIdx.x;

    float4* buf[2] = { (float4*)dynbuf, (float4*)(dynbuf + ROWBYTES) };
    uint32_t mbar[2] = { smem_u32(&s_mbar[0]), smem_u32(&s_mbar[1]) };
    uint32_t sdst[2] = { smem_u32(buf[0]), smem_u32(buf[1]) };

    if (tid < 32) hist32[tid] = 0;
    if (tid == 0) {
        s_cnt = 0; s_nf = 0;
        asm volatile("mbarrier.init.shared.b64 [%0], 1;" :: "r"(mbar[0]) : "memory");
        asm volatile("mbarrier.init.shared.b64 [%0], 1;" :: "r"(mbar[1]) : "memory");
    }
    __syncthreads();

    // prologue: launch TMAs for row(bid) -> buf0 and row(bid+G) -> buf1
    if (tid == 0) {
        const float* p0 = att + (size_t)bid * ROWLEN;
        asm volatile("mbarrier.arrive.expect_tx.shared.b64 _, [%0], %1;"
                     :: "r"(mbar[0]), "r"((uint32_t)ROWBYTES) : "memory");
        asm volatile("cp.async.bulk.shared::cta.global.mbarrier::complete_tx::bytes "
                     "[%0], [%1], %2, [%3];"
                     :: "r"(sdst[0]), "l"(p0), "r"((uint32_t)ROWBYTES), "r"(mbar[0])
                     : "memory");
        if (bid + G_TOPK < ROWS) {
            const float* p1 = att + (size_t)(bid + G_TOPK) * ROWLEN;
            asm volatile("mbarrier.arrive.expect_tx.shared.b64 _, [%0], %1;"
                         :: "r"(mbar[1]), "r"((uint32_t)ROWBYTES) : "memory");
            asm volatile("cp.async.bulk.shared::cta.global.mbarrier::complete_tx::bytes "
                         "[%0], [%1], %2, [%3];"
                         :: "r"(sdst[1]), "l"(p1), "r"((uint32_t)ROWBYTES), "r"(mbar[1])
                         : "memory");
        }
    }

    int ph[2] = {0, 0};
    int it = 0;
    for (int r = bid; r < ROWS; r += G_TOPK, it++) {
        int c = it & 1;
        const float4* sb = buf[c];
        const float*  srow = (const float*)sb;

        // wait for this buffer's row
        asm volatile(
            "{\n\t.reg .pred P;\n\t"
            "WAITLP_%=:\n\t"
            "mbarrier.try_wait.parity.acquire.cta.shared::cta.b64 P, [%0], %1, 0x989680;\n\t"
            "@!P bra WAITLP_%=;\n\t"
            "}" :: "r"(mbar[c]), "r"(ph[c]) : "memory");
        ph[c] ^= 1;

        // ---- pass 1: filter from smem, speculative collect ----
        #pragma unroll
        for (int j = 0; j < 8; j++) {
            float4 v = sb[tid + TPB * j];
            float m = fmaxf(fmaxf(v.x, v.y), fmaxf(v.z, v.w));
            if (m >= SPEC_F) {
                int g4 = (tid + TPB * j) * 4;
                if (v.x >= SPEC_F) { int q = atomicAdd(&s_cnt, 1);
                    if (q < CAP) cand[q] = __byte_perm(g4,     __float_as_uint(v.x), 0x7610) | 0x80000000u; }
                if (v.y >= SPEC_F) { int q = atomicAdd(&s_cnt, 1);
                    if (q < CAP) cand[q] = __byte_perm(g4 + 1, __float_as_uint(v.y), 0x7610) | 0x80000000u; }
                if (v.z >= SPEC_F) { int q = atomicAdd(&s_cnt, 1);
                    if (q < CAP) cand[q] = __byte_perm(g4 + 2, __float_as_uint(v.z), 0x7610) | 0x80000000u; }
                if (v.w >= SPEC_F) { int q = atomicAdd(&s_cnt, 1);
                    if (q < CAP) cand[q] = __byte_perm(g4 + 3, __float_as_uint(v.w), 0x7610) | 0x80000000u; }
            }
        }
        __syncthreads();

        uint32_t base16;
        if (s_cnt >= K_TOP && s_cnt <= CAP) {
            base16 = BASE16_SP;        // common path: all v >= 2.5 captured
        } else {
            // ---- generic fallback (astronomically rare): smem re-scan ----
            hist[tid] = 0;
            __syncthreads();
            #pragma unroll
            for (int j = 0; j < 8; j++) {
                float4 v = sb[tid + TPB * j];
                atomicAdd(&hist[f2key(__float_as_uint(v.x)) >> 24], 1u);
                atomicAdd(&hist[f2key(__float_as_uint(v.y)) >> 24], 1u);
                atomicAdd(&hist[f2key(__float_as_uint(v.z)) >> 24], 1u);
                atomicAdd(&hist[f2key(__float_as_uint(v.w)) >> 24], 1u);
            }
            __syncthreads();
            {
                uint32_t a = hist[tid];
                #pragma unroll
                for (int off = 1; off < 32; off <<= 1) {
                    uint32_t t = __shfl_down_sync(0xffffffffu, a, off);
                    if (lane + off < 32) a += t;
                }
                if (lane == 0) wsfx[wid] = a;
                __syncthreads();
                uint32_t add = 0;
                for (int w = wid + 1; w < 8; w++) add += wsfx[w];
                sfx[tid] = a + add;
                if (tid == 0) sfx[256] = 0;
            }
            __syncthreads();
            if (sfx[tid] >= K_TOP && sfx[tid + 1] < K_TOP) s_cb8 = tid;
            __syncthreads();
            uint32_t cb8 = (uint32_t)s_cb8;
            if (tid == 0) s_cnt = 0;
            __syncthreads();
            #pragma unroll
            for (int j = 0; j < 8; j++) {
                int g4 = (tid + TPB * j) * 4;
                float4 v = sb[tid + TPB * j];
                uint32_t ks[4] = { f2key(__float_as_uint(v.x)), f2key(__float_as_uint(v.y)),
                                   f2key(__float_as_uint(v.z)), f2key(__float_as_uint(v.w)) };
                #pragma unroll
                for (int cc = 0; cc < 4; cc++) {
                    if ((ks[cc] >> 24) >= cb8) {
                        int q = atomicAdd(&s_cnt, 1);
                        if (q < CAP) cand[q] = (ks[cc] & 0xFFFF0000u) | (uint32_t)(g4 + cc);
                    }
                }
            }
            __syncthreads();
            base16 = cb8 << 8;
        }

        // ---- stage 2: 32-bin hist + 1-warp suffix scan ----
        int n = min(s_cnt, CAP);
        for (int p = tid; p < n; p += TPB) {
            uint32_t b = ((cand[p] >> 16) - base16) >> 2;
            if (b > 31u) b = 31u;
            atomicAdd(&hist32[b], 1u);
        }
        __syncthreads();
        if (tid < 32) {
            uint32_t a = hist32[lane];
            #pragma unroll
            for (int off = 1; off < 32; off <<= 1) {
                uint32_t t = __shfl_down_sync(0xffffffffu, a, off);
                if (lane + off < 32) a += t;
            }
            unsigned mb = __ballot_sync(0xffffffffu, a >= K_TOP);
            int b = mb ? (31 - __clz(mb)) : 0;
            if (lane == 0) s_thr16 = base16 + ((uint32_t)b << 2);
        }
        __syncthreads();
        uint32_t thrp = s_thr16 << 16;

        // ---- filter to finalists ----
        for (int p = tid; p < n; p += TPB) {
            uint32_t cc = cand[p];
            if (cc >= thrp) {
                int q = atomicAdd(&s_nf, 1);
                if (q < CAP2) fc[q] = (uint16_t)(cc & 0xFFFFu);
            }
        }
        __syncthreads();

        // ---- warp 0: exact selection + softmax ----
        if (wid == 0) {
            int nf = min(s_nf, CAP2);
            if (nf <= 32) {
                int col = 0; uint32_t k = 0;
                if (lane < nf) {
                    col = fc[lane];
                    k = f2key(__float_as_uint(srow[col]));
                }
                unsigned long long pkd = 0;
                if (lane < nf)
                    pkd = ((unsigned long long)k << 16) | (uint32_t)(8191 - col);
                int rank = 0;
                for (int j = 0; j < nf; j++) {
                    unsigned long long pj = __shfl_sync(0xffffffffu, pkd, j);
                    rank += (pj > pkd) ? 1 : 0;
                }
                bool sel = (lane < nf) && (rank < K_TOP);
                unsigned mb = __ballot_sync(0xffffffffu, rank == 0);
                uint32_t kmax = __shfl_sync(0xffffffffu, k, __ffs(mb) - 1);
                float mx = key2f(kmax);
                float e = sel ? __expf(key2f(k) - mx) : 0.f;
                float s = e;
                #pragma unroll
                for (int off = 16; off; off >>= 1)
                    s += __shfl_xor_sync(0xffffffffu, s, off);
                if (sel) { s_w[rank] = e / s; seli[rank] = col; }
            } else {
                for (int p = lane; p < nf; p += 32)
                    fkk[p] = f2key(__float_as_uint(srow[fc[p]]));
                __syncwarp();
                for (int rr = 0; rr < 16; rr++) {
                    uint32_t bk = 0; int bIdx = 0x7FFFFFFF; int bSlot = -1;
                    for (int p = lane; p < nf; p += 32) {
                        uint32_t kk2 = fkk[p];
                        int      ii  = fc[p];
                        if (kk2 > bk || (kk2 == bk && kk2 != 0 && ii < bIdx)) { bk = kk2; bIdx = ii; bSlot = p; }
                    }
                    #pragma unroll
                    for (int off = 16; off; off >>= 1) {
                        uint32_t ok = __shfl_xor_sync(0xffffffffu, bk, off);
                        int      oi = __shfl_xor_sync(0xffffffffu, bIdx, off);
                        int      os = __shfl_xor_sync(0xffffffffu, bSlot, off);
                        if (ok > bk || (ok == bk && oi < bIdx)) { bk = ok; bIdx = oi; bSlot = os; }
                    }
                    if (lane == 0) {
                        selk[rr] = bk; seli[rr] = bIdx;
                        if (bSlot >= 0) fkk[bSlot] = 0;
                    }
                    __syncwarp();
                }
                float mx = key2f(selk[0]);
                float e = (lane < 16) ? __expf(key2f(selk[lane]) - mx) : 0.f;
                float s = e;
                #pragma unroll
                for (int off = 16; off; off >>= 1)
                    s += __shfl_xor_sync(0xffffffffu, s, off);
                if (lane < 16) s_w[lane] = e / s;
            }
        }
        __syncthreads();

        // ---- epilogue: out[n2, c*64+f] = sum_k w[k] * h[idx[k]][f] ----
        {
            int f   = tid & 63;
            int ks4 = tid >> 6;
            float acc = 0.f;
            #pragma unroll
            for (int k = 0; k < 4; k++) {
                int kk = ks4 * 4 + k;
                acc = fmaf(s_w[kk], g_h[(size_t)seli[kk] * F_OUT + f], acc);
            }
            partial[ks4][f] = acc;
        }
        __syncthreads();
        if (tid < 64) {
            float acc = partial[0][tid] + partial[1][tid] + partial[2][tid] + partial[3][tid];
            int ch = r >> 13;
            int n2 = r & (N_V - 1);
            out[(size_t)n2 * (C_CH * F_OUT) + ch * F_OUT + tid] = acc;
        }

        // ---- reset per-row state, then re-arm this buffer for row r+2G ----
        if (tid < 32) hist32[tid] = 0;
        if (tid == 0) { s_cnt = 0; s_nf = 0; }
        __syncthreads();   // all threads done with buf c + resets visible
        if (tid == 0 && r + 2 * G_TOPK < ROWS) {
            const float* pn = att + (size_t)(r + 2 * G_TOPK) * ROWLEN;
            asm volatile("mbarrier.arrive.expect_tx.shared.b64 _, [%0], %1;"
                         :: "r"(mbar[c]), "r"((uint32_t)ROWBYTES) : "memory");
            asm volatile("cp.async.bulk.shared::cta.global.mbarrier::complete_tx::bytes "
                         "[%0], [%1], %2, [%3];"
                         :: "r"(sdst[c]), "l"(pn), "r"((uint32_t)ROWBYTES), "r"(mbar[c])
                         : "memory");
        }
    }
}

// ---------------------------------------------------------------------------
extern "C" void kernel_launch(void* const* d_in, const int* in_sizes, int n_in,
                              void* d_out, int out_size) {
    const float* x   = (const float*)d_in[0];   // [8192, 512]
    const float* W   = (const float*)d_in[1];   // [512, 64]
    const float* att = (const float*)d_in[2];   // [32768, 8192]
    float* out = (float*)d_out;                 // [8192, 256]

    cudaFuncSetAttribute(topk_kernel,
                         cudaFuncAttributeMaxDynamicSharedMemorySize, 2 * ROWBYTES);

    gemm_kernel<<<N_V / BM, TPB>>>(x, W);
    topk_kernel<<<G_TOPK, TPB, 2 * ROWBYTES>>>(att, out);
}

// round 16
// speedup vs baseline: 1.4100x; 1.4100x over previous
#include <cuda_runtime.h>
#include <cstdint>

#define N_V   8192
#define C_CH  4
#define F_IN  512
#define F_OUT 64
#define K_TOP 16
#define ROWS  (N_V * C_CH)      // 32768
#define ROWLEN N_V              // 8192 attention cols per row
#define TPB   256
#define CAP   512               // candidate buffer (expected ~51, sigma ~7)
#define CAP2  256               // post-threshold candidates

#define SPEC_F     2.5f         // speculative floor; p=0.0062 per element
#define BASE16_SP  0xC020u      // keyhi16 of 2.5f: (0x4020 | 0x8000)

// scratch for h = x @ W   (2 MB static device array; no allocation)
__device__ float g_h[N_V * F_OUT];

// monotone key transform: order-preserving float -> uint
__device__ __forceinline__ uint32_t f2key(uint32_t b) {
    return b ^ ((uint32_t)((int32_t)b >> 31) | 0x80000000u);
}
__device__ __forceinline__ float key2f(uint32_t k) {
    uint32_t b = (k & 0x80000000u) ? (k ^ 0x80000000u) : ~k;
    return __uint_as_float(b);
}

// ---------------------------------------------------------------------------
// GEMM: h[8192,64] = x[8192,512] @ W[512,64]
// 64x64 block tile, 4x4 micro-tile, BK=32, k-unrolled by 4, register
// double-buffered GMEM loads (chunk k+1 LDGs issued before chunk k compute).
// ---------------------------------------------------------------------------
#define BM 64
#define BK 32
#define NCHUNK (F_IN / BK)     // 16
__global__ __launch_bounds__(TPB) void gemm_kernel(const float* __restrict__ x,
                                                   const float* __restrict__ W) {
    __shared__ float xs[BM][BK + 4];
    __shared__ float ws[BK][F_OUT];
    int tid = threadIdx.x;
    int tx = tid & 15;
    int ty = tid >> 4;
    int r0 = blockIdx.x * BM;

    // per-thread load coordinates (fixed across chunks)
    int xrow0 = tid >> 3,          xk4_0 = tid & 7;          // x float4 #0
    int xrow1 = (tid + TPB) >> 3,  xk4_1 = tid & 7;          // x float4 #1
    int wkk0  = tid >> 4,          wf4_0 = tid & 15;         // W float4 #0
    int wkk1  = (tid + TPB) >> 4,  wf4_1 = tid & 15;         // W float4 #1

    float acc[4][4];
    #pragma unroll
    for (int i = 0; i < 4; i++)
        #pragma unroll
        for (int j = 0; j < 4; j++) acc[i][j] = 0.f;

    // prologue: load chunk 0 into registers
    float4 rx0 = *(const float4*)(x + (size_t)(r0 + xrow0) * F_IN + xk4_0 * 4);
    float4 rx1 = *(const float4*)(x + (size_t)(r0 + xrow1) * F_IN + xk4_1 * 4);
    float4 rw0 = *(const float4*)(W + (size_t)wkk0 * F_OUT + wf4_0 * 4);
    float4 rw1 = *(const float4*)(W + (size_t)wkk1 * F_OUT + wf4_1 * 4);

    for (int ch = 0; ch < NCHUNK; ch++) {
        // stage current chunk into smem
        *(float4*)&xs[xrow0][xk4_0 * 4] = rx0;
        *(float4*)&xs[xrow1][xk4_1 * 4] = rx1;
        *(((float4*)&ws[wkk0][0]) + wf4_0) = rw0;
        *(((float4*)&ws[wkk1][0]) + wf4_1) = rw1;
        __syncthreads();

        // issue next chunk's loads immediately (overlap with compute below)
        if (ch + 1 < NCHUNK) {
            int k0n = (ch + 1) * BK;
            rx0 = *(const float4*)(x + (size_t)(r0 + xrow0) * F_IN + k0n + xk4_0 * 4);
            rx1 = *(const float4*)(x + (size_t)(r0 + xrow1) * F_IN + k0n + xk4_1 * 4);
            rw0 = *(const float4*)(W + (size_t)(k0n + wkk0) * F_OUT + wf4_0 * 4);
            rw1 = *(const float4*)(W + (size_t)(k0n + wkk1) * F_OUT + wf4_1 * 4);
        }

        #pragma unroll
        for (int kk0 = 0; kk0 < BK; kk0 += 4) {
            float4 a0 = *(const float4*)&xs[ty * 4 + 0][kk0];
            float4 a1 = *(const float4*)&xs[ty * 4 + 1][kk0];
            float4 a2 = *(const float4*)&xs[ty * 4 + 2][kk0];
            float4 a3 = *(const float4*)&xs[ty * 4 + 3][kk0];
            float4 b0 = *(((const float4*)&ws[kk0 + 0][0]) + tx);
            float4 b1 = *(((const float4*)&ws[kk0 + 1][0]) + tx);
            float4 b2 = *(((const float4*)&ws[kk0 + 2][0]) + tx);
            float4 b3 = *(((const float4*)&ws[kk0 + 3][0]) + tx);
            #define FMA4(ai, bq) \
                acc[0][0]=fmaf(a0.ai,bq.x,acc[0][0]); acc[0][1]=fmaf(a0.ai,bq.y,acc[0][1]); \
                acc[0][2]=fmaf(a0.ai,bq.z,acc[0][2]); acc[0][3]=fmaf(a0.ai,bq.w,acc[0][3]); \
                acc[1][0]=fmaf(a1.ai,bq.x,acc[1][0]); acc[1][1]=fmaf(a1.ai,bq.y,acc[1][1]); \
                acc[1][2]=fmaf(a1.ai,bq.z,acc[1][2]); acc[1][3]=fmaf(a1.ai,bq.w,acc[1][3]); \
                acc[2][0]=fmaf(a2.ai,bq.x,acc[2][0]); acc[2][1]=fmaf(a2.ai,bq.y,acc[2][1]); \
                acc[2][2]=fmaf(a2.ai,bq.z,acc[2][2]); acc[2][3]=fmaf(a2.ai,bq.w,acc[2][3]); \
                acc[3][0]=fmaf(a3.ai,bq.x,acc[3][0]); acc[3][1]=fmaf(a3.ai,bq.y,acc[3][1]); \
                acc[3][2]=fmaf(a3.ai,bq.z,acc[3][2]); acc[3][3]=fmaf(a3.ai,bq.w,acc[3][3]);
            FMA4(x, b0)
            FMA4(y, b1)
            FMA4(z, b2)
            FMA4(w, b3)
            #undef FMA4
        }
        __syncthreads();
    }
    #pragma unroll
    for (int i = 0; i < 4; i++) {
        float4 o = make_float4(acc[i][0], acc[i][1], acc[i][2], acc[i][3]);
        *(float4*)(g_h + (size_t)(r0 + ty * 4 + i) * F_OUT + tx * 4) = o;
    }
}

// ---------------------------------------------------------------------------
// Per-row top-16 via speculative threshold (v >= 2.5) + exact refinement.
// One block (256 thr) per row; pass 1 uses two groups of 4 front-loaded LDG.128
// (MLP=4) at 6 blocks/SM.   [R13 code, verbatim]
// ---------------------------------------------------------------------------
__global__ __launch_bounds__(TPB, 6) void topk_kernel(const float* __restrict__ att,
                                                      float* __restrict__ out) {
    __shared__ uint32_t cand[CAP];     // packed: keyhi16<<16 | col
    __shared__ uint32_t hist32[32];    // common-path 32-bin hist
    __shared__ uint32_t hist[256];     // fallback coarse hist
    __shared__ uint32_t sfx[257];      // fallback suffix scan
    __shared__ uint32_t wsfx[8];
    __shared__ int      s_cnt;
    __shared__ int      s_nf;
    __shared__ uint32_t s_thr16;
    __shared__ int      s_cb8;
    __shared__ uint16_t fc[CAP2];      // finalist columns
    __shared__ uint32_t fkk[CAP2];     // finalist full keys (slow path only)
    __shared__ uint32_t selk[16];
    __shared__ int      seli[16];
    __shared__ float    s_w[16];
    __shared__ float    partial[4][64];

    int tid  = threadIdx.x;
    int lane = tid & 31;
    int wid  = tid >> 5;
    int r    = blockIdx.x;
    const float*  rowp = att + (size_t)r * ROWLEN;
    const float4* row4 = (const float4*)(rowp);

    if (tid < 32) hist32[tid] = 0;
    if (tid == 0) { s_cnt = 0; s_nf = 0; }

    // ---- pass 1: two groups of 4 front-loaded LDG.128 + speculative collect ----
    {
        float4 v[4];
        #pragma unroll
        for (int j = 0; j < 4; j++)
            v[j] = __ldcs(&row4[tid + TPB * j]);
        __syncthreads();   // orders smem init vs atomics; group-0 loads already issued

        #pragma unroll
        for (int jb = 0; jb < 2; jb++) {
            #pragma unroll
            for (int j = 0; j < 4; j++) {
                float4 vj = v[j];
                // immediately start next group's load in this register slot
                if (jb == 0) v[j] = __ldcs(&row4[tid + TPB * (4 + j)]);
                float m = fmaxf(fmaxf(vj.x, vj.y), fmaxf(vj.z, vj.w));
                if (m >= SPEC_F) {
                    int g4 = (tid + TPB * (jb * 4 + j)) * 4;
                    if (vj.x >= SPEC_F) { int q = atomicAdd(&s_cnt, 1);
                        if (q < CAP) cand[q] = __byte_perm(g4,     __float_as_uint(vj.x), 0x7610) | 0x80000000u; }
                    if (vj.y >= SPEC_F) { int q = atomicAdd(&s_cnt, 1);
                        if (q < CAP) cand[q] = __byte_perm(g4 + 1, __float_as_uint(vj.y), 0x7610) | 0x80000000u; }
                    if (vj.z >= SPEC_F) { int q = atomicAdd(&s_cnt, 1);
                        if (q < CAP) cand[q] = __byte_perm(g4 + 2, __float_as_uint(vj.z), 0x7610) | 0x80000000u; }
                    if (vj.w >= SPEC_F) { int q = atomicAdd(&s_cnt, 1);
                        if (q < CAP) cand[q] = __byte_perm(g4 + 3, __float_as_uint(vj.w), 0x7610) | 0x80000000u; }
                }
            }
        }
    }
    __syncthreads();

    uint32_t base16;
    if (s_cnt >= K_TOP && s_cnt <= CAP) {
        base16 = BASE16_SP;            // common path: all v >= 2.5 captured
    } else {
        // ---- generic fallback (astronomically rare on this data): L2 re-scan ----
        hist[tid] = 0;
        __syncthreads();
        #pragma unroll
        for (int j = 0; j < 8; j++) {
            float4 v = row4[tid + TPB * j];
            atomicAdd(&hist[f2key(__float_as_uint(v.x)) >> 24], 1u);
            atomicAdd(&hist[f2key(__float_as_uint(v.y)) >> 24], 1u);
            atomicAdd(&hist[f2key(__float_as_uint(v.z)) >> 24], 1u);
            atomicAdd(&hist[f2key(__float_as_uint(v.w)) >> 24], 1u);
        }
        __syncthreads();
        {
            uint32_t a = hist[tid];
            #pragma unroll
            for (int off = 1; off < 32; off <<= 1) {
                uint32_t t = __shfl_down_sync(0xffffffffu, a, off);
                if (lane + off < 32) a += t;
            }
            if (lane == 0) wsfx[wid] = a;
            __syncthreads();
            uint32_t add = 0;
            for (int w = wid + 1; w < 8; w++) add += wsfx[w];
            sfx[tid] = a + add;
            if (tid == 0) sfx[256] = 0;
        }
        __syncthreads();
        if (sfx[tid] >= K_TOP && sfx[tid + 1] < K_TOP) s_cb8 = tid;
        __syncthreads();
        uint32_t cb8 = (uint32_t)s_cb8;
        if (tid == 0) s_cnt = 0;
        __syncthreads();
        #pragma unroll
        for (int j = 0; j < 8; j++) {
            int g4 = (tid + TPB * j) * 4;
            float4 v = row4[tid + TPB * j];
            uint32_t ks[4] = { f2key(__float_as_uint(v.x)), f2key(__float_as_uint(v.y)),
                               f2key(__float_as_uint(v.z)), f2key(__float_as_uint(v.w)) };
            #pragma unroll
            for (int c = 0; c < 4; c++) {
                if ((ks[c] >> 24) >= cb8) {
                    int q = atomicAdd(&s_cnt, 1);
                    if (q < CAP) cand[q] = (ks[c] & 0xFFFF0000u) | (uint32_t)(g4 + c);
                }
            }
        }
        __syncthreads();
        base16 = cb8 << 8;
    }

    // ---- stage 2: 32-bin hist (width 4 in key16 space) + 1-warp suffix scan ----
    int n = min(s_cnt, CAP);
    for (int p = tid; p < n; p += TPB) {
        uint32_t b = ((cand[p] >> 16) - base16) >> 2;
        if (b > 31u) b = 31u;
        atomicAdd(&hist32[b], 1u);
    }
    __syncthreads();
    if (tid < 32) {
        uint32_t a = hist32[lane];
        #pragma unroll
        for (int off = 1; off < 32; off <<= 1) {
            uint32_t t = __shfl_down_sync(0xffffffffu, a, off);
            if (lane + off < 32) a += t;
        }
        unsigned mb = __ballot_sync(0xffffffffu, a >= K_TOP);
        int b = mb ? (31 - __clz(mb)) : 0;
        if (lane == 0) s_thr16 = base16 + ((uint32_t)b << 2);
    }
    __syncthreads();
    uint32_t thrp = s_thr16 << 16;

    // ---- filter to finalists (>=16 by construction, expected ~16-25) ----
    for (int p = tid; p < n; p += TPB) {
        uint32_t c = cand[p];
        if (c >= thrp) {
            int q = atomicAdd(&s_nf, 1);
            if (q < CAP2) fc[q] = (uint16_t)(c & 0xFFFFu);
        }
    }
    __syncthreads();

    // ---- warp 0: exact selection on re-fetched fp32 values + softmax ----
    if (wid == 0) {
        int nf = min(s_nf, CAP2);
        if (nf <= 32) {
            // rank-based: lane l holds finalist l; rank by (key desc, col asc)
            int col = 0; uint32_t k = 0;
            if (lane < nf) {
                col = fc[lane];
                k = f2key(__float_as_uint(__ldg(&rowp[col])));
            }
            unsigned long long pkd = 0;
            if (lane < nf)
                pkd = ((unsigned long long)k << 16) | (uint32_t)(8191 - col);
            int rank = 0;
            for (int j = 0; j < nf; j++) {
                unsigned long long pj = __shfl_sync(0xffffffffu, pkd, j);
                rank += (pj > pkd) ? 1 : 0;
            }
            bool sel = (lane < nf) && (rank < K_TOP);
            unsigned mb = __ballot_sync(0xffffffffu, rank == 0);
            uint32_t kmax = __shfl_sync(0xffffffffu, k, __ffs(mb) - 1);
            float mx = key2f(kmax);
            float e = sel ? __expf(key2f(k) - mx) : 0.f;
            float s = e;
            #pragma unroll
            for (int off = 16; off; off >>= 1)
                s += __shfl_xor_sync(0xffffffffu, s, off);
            if (sel) { s_w[rank] = e / s; seli[rank] = col; }
        } else {
            // slow path: 16 argmax rounds (tie-break lowest column)
            for (int p = lane; p < nf; p += 32)
                fkk[p] = f2key(__float_as_uint(rowp[fc[p]]));
            __syncwarp();
            for (int rr = 0; rr < 16; rr++) {
                uint32_t bk = 0; int bIdx = 0x7FFFFFFF; int bSlot = -1;
                for (int p = lane; p < nf; p += 32) {
                    uint32_t kk2 = fkk[p];
                    int      ii  = fc[p];
                    if (kk2 > bk || (kk2 == bk && kk2 != 0 && ii < bIdx)) { bk = kk2; bIdx = ii; bSlot = p; }
                }
                #pragma unroll
                for (int off = 16; off; off >>= 1) {
                    uint32_t ok = __shfl_xor_sync(0xffffffffu, bk, off);
                    int      oi = __shfl_xor_sync(0xffffffffu, bIdx, off);
                    int      os = __shfl_xor_sync(0xffffffffu, bSlot, off);
                    if (ok > bk || (ok == bk && oi < bIdx)) { bk = ok; bIdx = oi; bSlot = os; }
                }
                if (lane == 0) {
                    selk[rr] = bk; seli[rr] = bIdx;
                    if (bSlot >= 0) fkk[bSlot] = 0;
                }
                __syncwarp();
            }
            float mx = key2f(selk[0]);
            float e = (lane < 16) ? __expf(key2f(selk[lane]) - mx) : 0.f;
            float s = e;
            #pragma unroll
            for (int off = 16; off; off >>= 1)
                s += __shfl_xor_sync(0xffffffffu, s, off);
            if (lane < 16) s_w[lane] = e / s;
        }
    }
    __syncthreads();

    // ---- epilogue: out[n, c*64+f] = sum_k w[k] * h[idx[k]][f] ----
    {
        int f   = tid & 63;
        int ks4 = tid >> 6;
        float acc = 0.f;
        #pragma unroll
        for (int k = 0; k < 4; k++) {
            int kk = ks4 * 4 + k;
            acc = fmaf(s_w[kk], g_h[(size_t)seli[kk] * F_OUT + f], acc);
        }
        partial[ks4][f] = acc;
    }
    __syncthreads();
    if (tid < 64) {
        float acc = partial[0][tid] + partial[1][tid] + partial[2][tid] + partial[3][tid];
        int c  = r >> 13;
        int n2 = r & (N_V - 1);
        out[(size_t)n2 * (C_CH * F_OUT) + c * F_OUT + tid] = acc;
    }
}

// ---------------------------------------------------------------------------
extern "C" void kernel_launch(void* const* d_in, const int* in_sizes, int n_in,
                              void* d_out, int out_size) {
    const float* x   = (const float*)d_in[0];   // [8192, 512]
    const float* W   = (const float*)d_in[1];   // [512, 64]
    const float* att = (const float*)d_in[2];   // [32768, 8192]
    float* out = (float*)d_out;                 // [8192, 256]

    gemm_kernel<<<N_V / BM, TPB>>>(x, W);
    topk_kernel<<<ROWS, TPB>>>(att, out);
}